// round 7
// baseline (speedup 1.0000x reference)
#include <cuda_runtime.h>

#define FULL 0xffffffffu

// ---------------- scratch ----------------------------------------------------
__device__ float    g_F[81 * 8];   // grid evaluations of <Z_j>, layout [n][j]
__device__ unsigned g_ctr;         // producer done-counter (reset by init_kernel)

// ---------------- warp statevector simulation (phase A only) ----------------
struct St { float2 a[8]; };

__device__ __forceinline__ float2 shxor(float2 v, int m) {
    float2 r;
    r.x = __shfl_xor_sync(FULL, v.x, m);
    r.y = __shfl_xor_sync(FULL, v.y, m);
    return r;
}

template<int Q>
__device__ __forceinline__ void gateRY(St& st, float c, float s, int lane) {
    if constexpr (Q >= 5) {
        constexpr int bit = 1 << (7 - Q);
#pragma unroll
        for (int m = 0; m < 8; ++m) {
            if ((m & bit) == 0) {
                float2 a = st.a[m], b = st.a[m | bit];
                st.a[m]       = make_float2(c * a.x - s * b.x, c * a.y - s * b.y);
                st.a[m | bit] = make_float2(s * a.x + c * b.x, s * a.y + c * b.y);
            }
        }
    } else {
        constexpr int lm = 1 << (4 - Q);
        float sg = (lane & lm) ? s : -s;
#pragma unroll
        for (int m = 0; m < 8; ++m) {
            float2 o = shxor(st.a[m], lm);
            float2 a = st.a[m];
            st.a[m] = make_float2(c * a.x + sg * o.x, c * a.y + sg * o.y);
        }
    }
}

template<int Q>
__device__ __forceinline__ void gateRX(St& st, float c, float s, int lane) {
    if constexpr (Q >= 5) {
        constexpr int bit = 1 << (7 - Q);
#pragma unroll
        for (int m = 0; m < 8; ++m) {
            if ((m & bit) == 0) {
                float2 a = st.a[m], b = st.a[m | bit];
                st.a[m]       = make_float2(c * a.x + s * b.y, c * a.y - s * b.x);
                st.a[m | bit] = make_float2(c * b.x + s * a.y, c * b.y - s * a.x);
            }
        }
    } else {
        constexpr int lm = 1 << (4 - Q);
#pragma unroll
        for (int m = 0; m < 8; ++m) {
            float2 o = shxor(st.a[m], lm);
            float2 a = st.a[m];
            st.a[m] = make_float2(c * a.x + s * o.y, c * a.y - s * o.x);
        }
    }
}

template<int Q>
__device__ __forceinline__ void gateRZ(St& st, float c, float s, int lane) {
    if constexpr (Q >= 5) {
        constexpr int bit = 1 << (7 - Q);
#pragma unroll
        for (int m = 0; m < 8; ++m) {
            float f = (m & bit) ? s : -s;
            float2 a = st.a[m];
            st.a[m] = make_float2(c * a.x - f * a.y, c * a.y + f * a.x);
        }
    } else {
        constexpr int lm = 1 << (4 - Q);
        float f = (lane & lm) ? s : -s;
#pragma unroll
        for (int m = 0; m < 8; ++m) {
            float2 a = st.a[m];
            st.a[m] = make_float2(c * a.x - f * a.y, c * a.y + f * a.x);
        }
    }
}

template<int C, int T>
__device__ __forceinline__ void cnot(St& st, int lane) {
    if constexpr (C <= 4 && T <= 4) {
        constexpr int cm = 1 << (4 - C);
        constexpr int tm = 1 << (4 - T);
        bool ctrl = (lane & cm) != 0;
#pragma unroll
        for (int m = 0; m < 8; ++m) {
            float2 o = shxor(st.a[m], tm);
            if (ctrl) st.a[m] = o;
        }
    } else if constexpr (C <= 4 && T >= 5) {
        constexpr int cm = 1 << (4 - C);
        constexpr int tb = 1 << (7 - T);
        bool ctrl = (lane & cm) != 0;
#pragma unroll
        for (int m = 0; m < 8; ++m) {
            if ((m & tb) == 0) {
                float2 a = st.a[m], b = st.a[m | tb];
                st.a[m]      = ctrl ? b : a;
                st.a[m | tb] = ctrl ? a : b;
            }
        }
    } else {
        constexpr int cb = 1 << (7 - C);
        constexpr int tb = 1 << (7 - T);
#pragma unroll
        for (int m = 0; m < 8; ++m) {
            if ((m & cb) != 0 && (m & tb) == 0) {
                float2 t = st.a[m];
                st.a[m] = st.a[m | tb];
                st.a[m | tb] = t;
            }
        }
    }
}

template<int J>
__device__ __forceinline__ void ansatzStep(St& st, const float* cw, const float* sw, int lane) {
    constexpr int C = (J < 7) ? J : 0;
    constexpr int T = (J < 7) ? J + 1 : 7;
    float c = cw[J], s = sw[J];
    gateRX<J>(st, c, s, lane);
    cnot<C, T>(st, lane);
    gateRY<J>(st, c, s, lane);
    cnot<C, T>(st, lane);
    gateRZ<J>(st, c, s, lane);
}

__device__ __forceinline__ void ansatz(St& st, const float* cw, const float* sw, int lane) {
    ansatzStep<0>(st, cw, sw, lane);
    ansatzStep<1>(st, cw, sw, lane);
    ansatzStep<2>(st, cw, sw, lane);
    ansatzStep<3>(st, cw, sw, lane);
    ansatzStep<4>(st, cw, sw, lane);
    ansatzStep<5>(st, cw, sw, lane);
    ansatzStep<6>(st, cw, sw, lane);
    ansatzStep<7>(st, cw, sw, lane);
}

// ---------------- init: reset counter + seed bias ----------------------------
__global__ void init_kernel(const float* __restrict__ db, float* __restrict__ out) {
    if (threadIdx.x == 0) g_ctr = 0u;
    out[threadIdx.x] = db[0];       // 32 outputs, one per batch
}

// ---------------- mega kernel ------------------------------------------------
// 512 blocks x 256 threads, ALL resident (launch_bounds min 4 blocks/SM ->
// regs <= 64 -> capacity 148*4 = 592 >= 512). Blocks 0..80 produce g_F with
// warp 0; every block then flag-syncs and runs the fused trig-poly pipeline.
#define CH 64
#define NP (CH + 3)    // 67 layer-1 values (halo)
#define NX (CH + 6)    // 70 x-sincos values

__device__ __forceinline__ void build_t9(const float* cc, const float* ss,
                                         float* t01, float* t23) {
    float t0[3] = {1.f, cc[0], ss[0]};
    float t1[3] = {1.f, cc[1], ss[1]};
    float t2[3] = {1.f, cc[2], ss[2]};
    float t3[3] = {1.f, cc[3], ss[3]};
#pragma unroll
    for (int i = 0; i < 3; ++i)
#pragma unroll
        for (int j = 0; j < 3; ++j) {
            t01[i * 3 + j] = t0[i] * t1[j];
            t23[i * 3 + j] = t2[i] * t3[j];
        }
}

__global__ void __launch_bounds__(256, 4) mega_kernel(const float* __restrict__ x,
                                                      const float* __restrict__ weights,
                                                      const float* __restrict__ dw,
                                                      float* __restrict__ out) {
    __shared__ float cw[24], sw[24];     // circuit warp only
    __shared__ float coef[648];          // [ch][81], transformed in place
    __shared__ float xc[NX], xs[NX];     // sincos of input window
    __shared__ float ac[NP], as_[NP];    // sincos of layer-1 relu values
    __shared__ float red[8];

    int t = threadIdx.x;
    int lane = t & 31;
    int wid = t >> 5;
    int bid = blockIdx.x;                // 0..511
    int b  = bid >> 4;                   // batch 0..31
    int s0 = (bid & 15) * CH;            // layer-2 chunk start

    // ---- (all blocks, warps 2-4) x-window sincos: independent of g_F ----
    {
        int k = t - 64;
        if (k >= 0 && k < NX) {
            int l = s0 - 2 + k;
            float cv = 1.f, sv = 0.f;
            if (l >= 0 && l < 1024) __sincosf(x[b * 1024 + l], &sv, &cv);
            xc[k] = cv; xs[k] = sv;
        }
    }

    // ---- phase A: blocks 0..80, warp 0 simulates grid circuit n = bid ----
    if (bid < 81 && wid == 0) {
        if (lane < 24) {
            const float TWO_PI = 6.28318530717958647692f;
            float w = weights[lane];
            float wm = fmodf(w, TWO_PI);
            if (wm < 0.f) wm += TWO_PI;
            cw[lane] = cosf(0.5f * wm);
            sw[lane] = sinf(0.5f * wm);
        }
        __syncwarp();

        St st;
#pragma unroll
        for (int m = 0; m < 8; ++m) st.a[m] = make_float2(0.f, 0.f);
        if (lane == 0) st.a[0] = make_float2(1.f, 0.f);
        ansatz(st, &cw[0], &sw[0], lane);

        const float GC[3] = {1.f, 0.70710678118654752440f, 0.f};
        const float GS[3] = {0.f, 0.70710678118654752440f, 1.f};
        int n = bid;
        int k0 = n / 27, k1 = (n / 9) % 3, k2 = (n / 3) % 3, k3 = n % 3;
        gateRY<0>(st, GC[k0], GS[k0], lane);
        gateRY<1>(st, GC[k1], GS[k1], lane);
        gateRY<2>(st, GC[k2], GS[k2], lane);
        gateRY<3>(st, GC[k3], GS[k3], lane);

        ansatz(st, &cw[8],  &sw[8],  lane);
        ansatz(st, &cw[16], &sw[16], lane);

        float vj[8];
#pragma unroll
        for (int j = 0; j < 8; ++j) vj[j] = 0.f;
#pragma unroll
        for (int m = 0; m < 8; ++m) {
            float2 a = st.a[m];
            float p = a.x * a.x + a.y * a.y;
            int idx = (lane << 3) | m;
#pragma unroll
            for (int j = 0; j < 8; ++j) vj[j] += ((idx >> (7 - j)) & 1) ? -p : p;
        }
#pragma unroll
        for (int j = 0; j < 8; ++j) {
#pragma unroll
            for (int o = 16; o; o >>= 1) vj[j] += __shfl_xor_sync(FULL, vj[j], o);
        }
        if (lane == 0) {
#pragma unroll
            for (int j = 0; j < 8; ++j) g_F[n * 8 + j] = vj[j];
            __threadfence();                     // publish g_F before counting
            atomicAdd(&g_ctr, 1u);
        }
    }

    // ---- flag-sync: wait for all 81 producers (entire grid is resident) ----
    if (t == 255) {
        while (*(volatile unsigned*)&g_ctr < 81u) __nanosleep(128);
        __threadfence();                         // order spin before g_F reads
    }
    __syncthreads();

    // ---- load F transposed: coef[j*81+n] = g_F[n*8+j] ----
    for (int i = t; i < 648; i += 256) {
        int j = i / 81, n = i - j * 81;
        coef[i] = g_F[n * 8 + j];
    }
    __syncthreads();

    // ---- transform: per-axis {1,cos,sin} extraction, in place (4 passes) ----
#pragma unroll
    for (int a = 0; a < 4; ++a) {
        const int stv = (a == 0) ? 27 : (a == 1) ? 9 : (a == 2) ? 3 : 1;
        if (t < 216) {
            int j = t / 27, r = t - j * 27;
            int base = j * 81 + (r / stv) * (3 * stv) + (r % stv);
            float f0 = coef[base], f1 = coef[base + stv], f2 = coef[base + 2 * stv];
            float kc = 0.5f * (f0 + f2);
            coef[base]           = kc;
            coef[base + stv]     = 0.5f * (f0 - f2);
            coef[base + 2 * stv] = f1 - kc;
        }
        __syncthreads();
    }

    // ---- layer 1: thread-per-position (p = s0 - 1 + t) ----
    if (t < NP) {
        int p = s0 - 1 + t;
        float cv = 1.f, sv = 0.f;          // OOB position -> angle 0
        if (p >= 0 && p < 1023) {
            float t01[9], t23[9];
            build_t9(&xc[t], &xs[t], t01, t23);
            float v = 0.f;
#pragma unroll
            for (int i = 0; i < 9; ++i) {
                float pp = 0.f;
#pragma unroll
                for (int l = 0; l < 9; ++l) pp = fmaf(coef[i * 9 + l], t23[l], pp);
                v = fmaf(t01[i], pp, v);
            }
            __sincosf(fmaxf(v, 0.f), &sv, &cv);
        }
        ac[t] = cv; as_[t] = sv;
    }
    __syncthreads();

    // ---- layer 2: thread = (channel, 2 positions); coef LDS reused ----
    int ch = t & 7;
    int q  = t >> 3;                     // 0..31 -> local positions 2q, 2q+1
    int pA = 2 * q, pB = 2 * q + 1;
    float t01a[9], t23a[9], t01b[9], t23b[9];
    build_t9(&ac[pA], &as_[pA], t01a, t23a);
    build_t9(&ac[pB], &as_[pB], t01b, t23b);

    const float* sc = &coef[ch * 81];
    float acc0 = 0.f, acc1 = 0.f;
#pragma unroll
    for (int i = 0; i < 9; ++i) {
        float pa = 0.f, pb = 0.f;
#pragma unroll
        for (int l = 0; l < 9; ++l) {
            float c = sc[i * 9 + l];
            pa = fmaf(c, t23a[l], pa);
            pb = fmaf(c, t23b[l], pb);
        }
        acc0 = fmaf(t01a[i], pa, acc0);
        acc1 = fmaf(t01b[i], pb, acc1);
    }

    // channel max across octet (warp-uniform shuffles)
    acc0 = fmaxf(acc0, __shfl_xor_sync(FULL, acc0, 1));
    acc0 = fmaxf(acc0, __shfl_xor_sync(FULL, acc0, 2));
    acc0 = fmaxf(acc0, __shfl_xor_sync(FULL, acc0, 4));
    acc1 = fmaxf(acc1, __shfl_xor_sync(FULL, acc1, 1));
    acc1 = fmaxf(acc1, __shfl_xor_sync(FULL, acc1, 2));
    acc1 = fmaxf(acc1, __shfl_xor_sync(FULL, acc1, 4));

    // dense contributions (relu(max) == max(relu))
    float contrib = 0.f;
    if (ch == 0) {
        int sA = s0 + pA, sB = s0 + pB;
        if (sA < 1022) contrib += fmaxf(acc0, 0.f) * dw[sA];
        if (sB < 1022) contrib += fmaxf(acc1, 0.f) * dw[sB];
    }
    contrib += __shfl_xor_sync(FULL, contrib, 8);
    contrib += __shfl_xor_sync(FULL, contrib, 16);
    if (lane == 0) red[wid] = contrib;
    __syncthreads();
    if (wid == 0) {
        float r = (lane < 8) ? red[lane] : 0.f;
        r += __shfl_xor_sync(FULL, r, 1);
        r += __shfl_xor_sync(FULL, r, 2);
        r += __shfl_xor_sync(FULL, r, 4);
        if (lane == 0) atomicAdd(&out[b], r);
    }
}

// ---------------- launch ------------------------------------------------------
extern "C" void kernel_launch(void* const* d_in, const int* in_sizes, int n_in,
                              void* d_out, int out_size) {
    const float* x       = (const float*)d_in[0];   // (32,1024,1)
    const float* weights = (const float*)d_in[1];   // (3,8)
    const float* dw      = (const float*)d_in[2];   // (1022,1)
    const float* db      = (const float*)d_in[3];   // (1,)
    float* out = (float*)d_out;                     // (32,1)

    init_kernel<<<1, 32>>>(db, out);
    mega_kernel<<<512, 256>>>(x, weights, dw, out);
}

// round 8
// speedup vs baseline: 1.1510x; 1.1510x over previous
#include <cuda_runtime.h>

#define FULL 0xffffffffu

// ---------------- scratch ----------------------------------------------------
__device__ float g_F[81 * 8];     // grid evaluations of <Z_j>, layout [n][j]

// ---------------- warp statevector simulation (gridsim only) ----------------
struct St { float2 a[8]; };

__device__ __forceinline__ float2 shxor(float2 v, int m) {
    float2 r;
    r.x = __shfl_xor_sync(FULL, v.x, m);
    r.y = __shfl_xor_sync(FULL, v.y, m);
    return r;
}

template<int Q>
__device__ __forceinline__ void gateRY(St& st, float c, float s, int lane) {
    if constexpr (Q >= 5) {
        constexpr int bit = 1 << (7 - Q);
#pragma unroll
        for (int m = 0; m < 8; ++m) {
            if ((m & bit) == 0) {
                float2 a = st.a[m], b = st.a[m | bit];
                st.a[m]       = make_float2(c * a.x - s * b.x, c * a.y - s * b.y);
                st.a[m | bit] = make_float2(s * a.x + c * b.x, s * a.y + c * b.y);
            }
        }
    } else {
        constexpr int lm = 1 << (4 - Q);
        float sg = (lane & lm) ? s : -s;
#pragma unroll
        for (int m = 0; m < 8; ++m) {
            float2 o = shxor(st.a[m], lm);
            float2 a = st.a[m];
            st.a[m] = make_float2(c * a.x + sg * o.x, c * a.y + sg * o.y);
        }
    }
}

template<int Q>
__device__ __forceinline__ void gateRX(St& st, float c, float s, int lane) {
    if constexpr (Q >= 5) {
        constexpr int bit = 1 << (7 - Q);
#pragma unroll
        for (int m = 0; m < 8; ++m) {
            if ((m & bit) == 0) {
                float2 a = st.a[m], b = st.a[m | bit];
                st.a[m]       = make_float2(c * a.x + s * b.y, c * a.y - s * b.x);
                st.a[m | bit] = make_float2(c * b.x + s * a.y, c * b.y - s * a.x);
            }
        }
    } else {
        constexpr int lm = 1 << (4 - Q);
#pragma unroll
        for (int m = 0; m < 8; ++m) {
            float2 o = shxor(st.a[m], lm);
            float2 a = st.a[m];
            st.a[m] = make_float2(c * a.x + s * o.y, c * a.y - s * o.x);
        }
    }
}

template<int Q>
__device__ __forceinline__ void gateRZ(St& st, float c, float s, int lane) {
    if constexpr (Q >= 5) {
        constexpr int bit = 1 << (7 - Q);
#pragma unroll
        for (int m = 0; m < 8; ++m) {
            float f = (m & bit) ? s : -s;
            float2 a = st.a[m];
            st.a[m] = make_float2(c * a.x - f * a.y, c * a.y + f * a.x);
        }
    } else {
        constexpr int lm = 1 << (4 - Q);
        float f = (lane & lm) ? s : -s;
#pragma unroll
        for (int m = 0; m < 8; ++m) {
            float2 a = st.a[m];
            st.a[m] = make_float2(c * a.x - f * a.y, c * a.y + f * a.x);
        }
    }
}

template<int C, int T>
__device__ __forceinline__ void cnot(St& st, int lane) {
    if constexpr (C <= 4 && T <= 4) {
        constexpr int cm = 1 << (4 - C);
        constexpr int tm = 1 << (4 - T);
        bool ctrl = (lane & cm) != 0;
#pragma unroll
        for (int m = 0; m < 8; ++m) {
            float2 o = shxor(st.a[m], tm);
            if (ctrl) st.a[m] = o;
        }
    } else if constexpr (C <= 4 && T >= 5) {
        constexpr int cm = 1 << (4 - C);
        constexpr int tb = 1 << (7 - T);
        bool ctrl = (lane & cm) != 0;
#pragma unroll
        for (int m = 0; m < 8; ++m) {
            if ((m & tb) == 0) {
                float2 a = st.a[m], b = st.a[m | tb];
                st.a[m]      = ctrl ? b : a;
                st.a[m | tb] = ctrl ? a : b;
            }
        }
    } else {
        constexpr int cb = 1 << (7 - C);
        constexpr int tb = 1 << (7 - T);
#pragma unroll
        for (int m = 0; m < 8; ++m) {
            if ((m & cb) != 0 && (m & tb) == 0) {
                float2 t = st.a[m];
                st.a[m] = st.a[m | tb];
                st.a[m | tb] = t;
            }
        }
    }
}

template<int J>
__device__ __forceinline__ void ansatzStep(St& st, const float* cw, const float* sw, int lane) {
    constexpr int C = (J < 7) ? J : 0;
    constexpr int T = (J < 7) ? J + 1 : 7;
    float c = cw[J], s = sw[J];
    gateRX<J>(st, c, s, lane);
    cnot<C, T>(st, lane);
    gateRY<J>(st, c, s, lane);
    cnot<C, T>(st, lane);
    gateRZ<J>(st, c, s, lane);
}

__device__ __forceinline__ void ansatz(St& st, const float* cw, const float* sw, int lane) {
    ansatzStep<0>(st, cw, sw, lane);
    ansatzStep<1>(st, cw, sw, lane);
    ansatzStep<2>(st, cw, sw, lane);
    ansatzStep<3>(st, cw, sw, lane);
    ansatzStep<4>(st, cw, sw, lane);
    ansatzStep<5>(st, cw, sw, lane);
    ansatzStep<6>(st, cw, sw, lane);
    ansatzStep<7>(st, cw, sw, lane);
}

// ---------------- kernel 1: 81 grid circuits (each block self-contained) ----
__global__ void gridsim_kernel(const float* __restrict__ weights,
                               const float* __restrict__ db,
                               float* __restrict__ out) {
    __shared__ float cw[24], sw[24];
    int lane = threadIdx.x;

    if (blockIdx.x == 0) out[lane] = db[0];   // seed output with bias

    if (lane < 24) {
        const float TWO_PI = 6.28318530717958647692f;
        float w = weights[lane];
        float wm = fmodf(w, TWO_PI);
        if (wm < 0.f) wm += TWO_PI;
        cw[lane] = cosf(0.5f * wm);
        sw[lane] = sinf(0.5f * wm);
    }
    __syncwarp();

    St st;
#pragma unroll
    for (int m = 0; m < 8; ++m) st.a[m] = make_float2(0.f, 0.f);
    if (lane == 0) st.a[0] = make_float2(1.f, 0.f);
    ansatz(st, &cw[0], &sw[0], lane);

    const float GC[3] = {1.f, 0.70710678118654752440f, 0.f};
    const float GS[3] = {0.f, 0.70710678118654752440f, 1.f};
    int n = blockIdx.x;
    int k0 = n / 27, k1 = (n / 9) % 3, k2 = (n / 3) % 3, k3 = n % 3;
    gateRY<0>(st, GC[k0], GS[k0], lane);
    gateRY<1>(st, GC[k1], GS[k1], lane);
    gateRY<2>(st, GC[k2], GS[k2], lane);
    gateRY<3>(st, GC[k3], GS[k3], lane);

    ansatz(st, &cw[8],  &sw[8],  lane);
    ansatz(st, &cw[16], &sw[16], lane);

    float vj[8];
#pragma unroll
    for (int j = 0; j < 8; ++j) vj[j] = 0.f;
#pragma unroll
    for (int m = 0; m < 8; ++m) {
        float2 a = st.a[m];
        float p = a.x * a.x + a.y * a.y;
        int idx = (lane << 3) | m;
#pragma unroll
        for (int j = 0; j < 8; ++j) vj[j] += ((idx >> (7 - j)) & 1) ? -p : p;
    }
#pragma unroll
    for (int j = 0; j < 8; ++j) {
#pragma unroll
        for (int o = 16; o; o >>= 1) vj[j] += __shfl_xor_sync(FULL, vj[j], o);
    }
    if (lane == 0) {
#pragma unroll
        for (int j = 0; j < 8; ++j) g_F[n * 8 + j] = vj[j];
    }
}

// ---------------- kernel 2: transform + layer1 + layer2 + pool + dense ------
// 256 threads; thread = (channel = t&7, 4 positions 4q..4q+3, q = t>>3)
// block covers CH = 128 layer-2 positions; grid (8, 32)
#define CH 128
#define NP (CH + 3)    // 131 layer-1 values (halo)
#define NX (CH + 6)    // 134 x-sincos values

__global__ void __launch_bounds__(256) fused_kernel(const float* __restrict__ x,
                                                    const float* __restrict__ dw,
                                                    float* __restrict__ out) {
    __shared__ float coef[648];          // [ch][81], transformed in place
    __shared__ float xc[NX], xs[NX];     // sincos of input window
    __shared__ float ac[NP], as_[NP];    // sincos of layer-1 relu values
    __shared__ float red[8];

    int t = threadIdx.x;
    int lane = t & 31;
    int warp = t >> 5;
    int b = blockIdx.y;
    int s0 = blockIdx.x * CH;

    // --- load F transposed: coef[j*81+n] = g_F[n*8+j] ---
    for (int i = t; i < 648; i += 256) {
        int j = i / 81, n = i - j * 81;
        coef[i] = g_F[n * 8 + j];
    }
    // --- sincos of x window: x index l = s0-2+k ---
    if (t < NX) {
        int l = s0 - 2 + t;
        float cv = 1.f, sv = 0.f;
        if (l >= 0 && l < 1024) __sincosf(x[b * 1024 + l], &sv, &cv);
        xc[t] = cv; xs[t] = sv;
    }
    __syncthreads();

    // --- transform: per-axis {1,cos,sin} extraction, in place (4 passes) ---
#pragma unroll
    for (int a = 0; a < 4; ++a) {
        const int stv = (a == 0) ? 27 : (a == 1) ? 9 : (a == 2) ? 3 : 1;
        if (t < 216) {
            int j = t / 27, r = t - j * 27;
            int base = j * 81 + (r / stv) * (3 * stv) + (r % stv);
            float f0 = coef[base], f1 = coef[base + stv], f2 = coef[base + 2 * stv];
            float kc = 0.5f * (f0 + f2);
            coef[base]           = kc;
            coef[base + stv]     = 0.5f * (f0 - f2);
            coef[base + 2 * stv] = f1 - kc;
        }
        __syncthreads();
    }

    // --- layer 1: thread-per-position (p = s0 - 1 + t), t < NP=131 ---
    if (t < NP) {
        int p = s0 - 1 + t;
        float cv = 1.f, sv = 0.f;          // OOB position -> angle 0
        if (p >= 0 && p < 1023) {
            float t0c = xc[t],     t0s = xs[t];
            float t1c = xc[t + 1], t1s = xs[t + 1];
            float t23[9];
            {
                float t2[3] = {1.f, xc[t + 2], xs[t + 2]};
                float t3[3] = {1.f, xc[t + 3], xs[t + 3]};
#pragma unroll
                for (int i = 0; i < 3; ++i)
#pragma unroll
                    for (int j = 0; j < 3; ++j) t23[i * 3 + j] = t2[i] * t3[j];
            }
            float v = 0.f;
#pragma unroll
            for (int i = 0; i < 9; ++i) {
                float pp = 0.f;
#pragma unroll
                for (int l = 0; l < 9; ++l) pp = fmaf(coef[i * 9 + l], t23[l], pp);
                float f0 = (i < 3) ? 1.f : (i < 6) ? t0c : t0s;
                float f1 = (i % 3 == 0) ? 1.f : (i % 3 == 1) ? t1c : t1s;
                v = fmaf(f0 * f1, pp, v);
            }
            __sincosf(fmaxf(v, 0.f), &sv, &cv);
        }
        ac[t] = cv; as_[t] = sv;
    }
    __syncthreads();

    // --- layer 2: thread = (channel, 4 positions); sc row LDS feeds 4 chains
    int ch = t & 7;
    int q  = t >> 3;                     // 0..31 -> local positions 4q..4q+3
    int p0 = 4 * q;

    float t23[4][9];
    float c0[4], s0v[4], c1[4], s1v[4];
#pragma unroll
    for (int r = 0; r < 4; ++r) {
        int p = p0 + r;
        c0[r] = ac[p];     s0v[r] = as_[p];
        c1[r] = ac[p + 1]; s1v[r] = as_[p + 1];
        float t2[3] = {1.f, ac[p + 2], as_[p + 2]};
        float t3[3] = {1.f, ac[p + 3], as_[p + 3]};
#pragma unroll
        for (int i = 0; i < 3; ++i)
#pragma unroll
            for (int j = 0; j < 3; ++j) t23[r][i * 3 + j] = t2[i] * t3[j];
    }

    const float* sc = &coef[ch * 81];
    float acc[4] = {0.f, 0.f, 0.f, 0.f};
#pragma unroll
    for (int i = 0; i < 9; ++i) {
        float row[9];
#pragma unroll
        for (int l = 0; l < 9; ++l) row[l] = sc[i * 9 + l];
#pragma unroll
        for (int r = 0; r < 4; ++r) {
            float d = 0.f;
#pragma unroll
            for (int l = 0; l < 9; ++l) d = fmaf(row[l], t23[r][l], d);
            float f0 = (i < 3) ? 1.f : (i < 6) ? c0[r] : s0v[r];
            float f1 = (i % 3 == 0) ? 1.f : (i % 3 == 1) ? c1[r] : s1v[r];
            acc[r] = fmaf(f0 * f1, d, acc[r]);
        }
    }

    // channel max across octet (warp-uniform shuffles)
#pragma unroll
    for (int r = 0; r < 4; ++r) {
        acc[r] = fmaxf(acc[r], __shfl_xor_sync(FULL, acc[r], 1));
        acc[r] = fmaxf(acc[r], __shfl_xor_sync(FULL, acc[r], 2));
        acc[r] = fmaxf(acc[r], __shfl_xor_sync(FULL, acc[r], 4));
    }

    // dense contributions (relu(max) == max(relu))
    float contrib = 0.f;
    if (ch == 0) {
#pragma unroll
        for (int r = 0; r < 4; ++r) {
            int s = s0 + p0 + r;
            if (s < 1022) contrib += fmaxf(acc[r], 0.f) * dw[s];
        }
    }
    contrib += __shfl_xor_sync(FULL, contrib, 8);
    contrib += __shfl_xor_sync(FULL, contrib, 16);
    if (lane == 0) red[warp] = contrib;
    __syncthreads();
    if (warp == 0) {
        float r = (lane < 8) ? red[lane] : 0.f;
        r += __shfl_xor_sync(FULL, r, 1);
        r += __shfl_xor_sync(FULL, r, 2);
        r += __shfl_xor_sync(FULL, r, 4);
        if (lane == 0) atomicAdd(&out[b], r);
    }
}

// ---------------- launch ------------------------------------------------------
extern "C" void kernel_launch(void* const* d_in, const int* in_sizes, int n_in,
                              void* d_out, int out_size) {
    const float* x       = (const float*)d_in[0];   // (32,1024,1)
    const float* weights = (const float*)d_in[1];   // (3,8)
    const float* dw      = (const float*)d_in[2];   // (1022,1)
    const float* db      = (const float*)d_in[3];   // (1,)
    float* out = (float*)d_out;                     // (32,1)

    gridsim_kernel<<<81, 32>>>(weights, db, out);
    dim3 g((1022 + CH - 1) / CH, 32);               // (8, 32)
    fused_kernel<<<g, 256>>>(x, dw, out);
}